// round 13
// baseline (speedup 1.0000x reference)
#include <cuda_runtime.h>
#include <cuda_fp16.h>
#include <cstdint>

#define BB 8
#define TT 4096
#define DM 512

// projected Q, K, V scratch (fp16). Q pre-scaled by (1/sqrt(512))*log2(e).
// V stored TRANSPOSED: g_Vt[b][d][t]. g_Wt: W transposed fp16 [which][n][k].
__device__ __align__(256) __half g_Qh[BB * TT * 64];
__device__ __align__(256) __half g_Kh[BB * TT * 64];
__device__ __align__(256) __half g_Vt[BB * 64 * TT];
__device__ __align__(256) __half g_Wt[3 * 64 * DM];

// ---------------------------------------------------------------------------
// helpers
// ---------------------------------------------------------------------------
__device__ __forceinline__ uint32_t smem_to_u32(const void* p) {
    uint32_t a;
    asm("{ .reg .u64 t; cvta.to.shared.u64 t, %1; cvt.u32.u64 %0, t; }" : "=r"(a) : "l"(p));
    return a;
}
__device__ __forceinline__ uint32_t pack_h2(float lo, float hi) {
    uint32_t d; asm("cvt.rn.f16x2.f32 %0, %1, %2;" : "=r"(d) : "f"(hi), "f"(lo)); return d;
}
__device__ __forceinline__ uint32_t hadd2(uint32_t a, uint32_t b) {
    uint32_t d; asm("add.rn.f16x2 %0, %1, %2;" : "=r"(d) : "r"(a), "r"(b)); return d;
}
__device__ __forceinline__ uint32_t h2exp2(uint32_t a) {
    uint32_t d; asm("ex2.approx.f16x2 %0, %1;" : "=r"(d) : "r"(a)); return d;
}
// fp16: D += A(m16 x k16) * B(k16 x n8), f32 accumulate
__device__ __forceinline__ void mma16(float* d, const uint32_t* a, const uint32_t* b) {
    asm volatile(
        "mma.sync.aligned.m16n8k16.row.col.f32.f16.f16.f32 "
        "{%0,%1,%2,%3}, {%4,%5,%6,%7}, {%8,%9}, {%0,%1,%2,%3};"
        : "+f"(d[0]), "+f"(d[1]), "+f"(d[2]), "+f"(d[3])
        : "r"(a[0]), "r"(a[1]), "r"(a[2]), "r"(a[3]), "r"(b[0]), "r"(b[1]));
}
__device__ __forceinline__ void cp16(uint32_t dst, const void* src) {
    asm volatile("cp.async.ca.shared.global [%0], [%1], 16;" :: "r"(dst), "l"(src));
}
__device__ __forceinline__ void cp_commit() { asm volatile("cp.async.commit_group;"); }
template<int N> __device__ __forceinline__ void cp_wait() {
    asm volatile("cp.async.wait_group %0;" :: "n"(N));
}

// ---------------------------------------------------------------------------
// W pre-transpose: g_Wt[which][n][k] = fp16(W[k][n]). 24 blocks.
// ---------------------------------------------------------------------------
__global__ void __launch_bounds__(256) wconv_kernel(
    const float* __restrict__ Wq, const float* __restrict__ Wk,
    const float* __restrict__ Wv)
{
    __shared__ float tile[64][65];
    int which = blockIdx.x >> 3;
    int kb    = (blockIdx.x & 7) * 64;
    const float* W = (which == 0) ? Wq : ((which == 1) ? Wk : Wv);
    __half* Wt = g_Wt + (size_t)which * 64 * DM;
    int tid = threadIdx.x;

    #pragma unroll
    for (int i = 0; i < 16; i++) {
        int idx = tid + i * 256;
        int k = idx >> 6, n = idx & 63;
        tile[k][n] = W[(size_t)(kb + k) * 64 + n];
    }
    __syncthreads();
    #pragma unroll
    for (int i = 0; i < 16; i++) {
        int idx = tid + i * 256;
        int n = idx >> 6, k = idx & 63;
        Wt[(size_t)n * DM + kb + k] = __float2half_rn(tile[k][n]);
    }
}

// ---------------------------------------------------------------------------
// Projection: Y[32768,64] = X[32768,512] @ W[512,64], fp16 m16n8k16.
// 3-stage circular cp.async pipeline, ONE barrier per K-chunk; ~2-chunk
// latency window (covers DRAM latency).
// fp16 epilogue: which==0 -> g_Qh (scaled), 1 -> g_Kh, 2 -> g_Vt (transposed).
// ---------------------------------------------------------------------------
#define PX_PAD 36
#define PWT_STR 40
#define PX_BUF 18432
#define PW_BUF 5120
#define P_X(s) ((s) * PX_BUF)                  // s = 0..2
#define P_W(s) (3 * PX_BUF + (s) * PW_BUF)
#define P_TOT  (3 * PX_BUF + 3 * PW_BUF)       // 70656

__global__ void __launch_bounds__(256, 2) proj_kernel(
    const float* __restrict__ Xq, const float* __restrict__ Xk, const float* __restrict__ Xv)
{
    extern __shared__ char sm[];
    uint32_t smb = smem_to_u32(sm);

    const float* X;
    int which = blockIdx.y;
    if (which == 0)      X = Xq;
    else if (which == 1) X = Xk;
    else                 X = Xv;
    const __half* Wt = g_Wt + (size_t)which * 64 * DM;

    const int tid = threadIdx.x, lane = tid & 31, warp = tid >> 5;
    const int r4 = lane >> 2, k4 = lane & 3;
    const int rowBase = blockIdx.x * 128;

    auto load_chunk = [&](int ch) {
        int s = ch % 3;
        uint32_t xd = smb + P_X(s);
        uint32_t wd = smb + P_W(s);
        const float* xs = X + (size_t)rowBase * DM + ch * 32;
        #pragma unroll
        for (int i = 0; i < 4; i++) {
            int idx = tid + i * 256;
            int row = idx >> 3, c = idx & 7;
            cp16(xd + row * (PX_PAD * 4) + c * 16, xs + (size_t)row * DM + c * 4);
        }
        {
            int n = tid >> 2, seg = tid & 3;
            cp16(wd + n * (PWT_STR * 2) + seg * 16, Wt + (size_t)n * DM + ch * 32 + seg * 8);
        }
        cp_commit();
    };

    float acc[8][4];
    #pragma unroll
    for (int nb = 0; nb < 8; nb++)
        #pragma unroll
        for (int i = 0; i < 4; i++) acc[nb][i] = 0.0f;

    load_chunk(0);
    load_chunk(1);
    for (int ch = 0; ch < 16; ch++) {
        if (ch < 15) cp_wait<1>(); else cp_wait<0>();
        __syncthreads();          // chunk ch visible; all warps done with ch-1
        if (ch < 14) load_chunk(ch + 2);   // overwrites buffer of ch-1 (safe)

        const float*  Xs = (const float*)(sm + P_X(ch % 3));
        const __half* Ws = (const __half*)(sm + P_W(ch % 3));

        #pragma unroll
        for (int ks = 0; ks < 2; ks++) {
            int c0 = ks * 16 + 2 * k4;
            const float* xp  = Xs + (warp * 16 + r4) * PX_PAD + c0;
            const float* xp8 = xp + 8 * PX_PAD;
            uint32_t a[4] = {
                pack_h2(xp[0],  xp[1]),
                pack_h2(xp8[0], xp8[1]),
                pack_h2(xp[8],  xp[9]),
                pack_h2(xp8[8], xp8[9])
            };
            #pragma unroll
            for (int nb = 0; nb < 8; nb++) {
                const __half* wn = Ws + (nb * 8 + r4) * PWT_STR + c0;
                uint32_t bb[2] = { *(const uint32_t*)(wn), *(const uint32_t*)(wn + 8) };
                mma16(acc[nb], a, bb);
            }
        }
    }

    if (which == 2) {
        int m = rowBase + warp * 16 + r4;
        int bq = m >> 12;
        int t = m & 4095;
        #pragma unroll
        for (int nb = 0; nb < 8; nb++) {
            int d = nb * 8 + 2 * k4;
            g_Vt[((size_t)bq * 64 + d)     * TT + t]     = __float2half_rn(acc[nb][0]);
            g_Vt[((size_t)bq * 64 + d + 1) * TT + t]     = __float2half_rn(acc[nb][1]);
            g_Vt[((size_t)bq * 64 + d)     * TT + t + 8] = __float2half_rn(acc[nb][2]);
            g_Vt[((size_t)bq * 64 + d + 1) * TT + t + 8] = __float2half_rn(acc[nb][3]);
        }
    } else {
        __half* Yh = (which == 0) ? g_Qh : g_Kh;
        const float sc = (which == 0)
            ? (0.044194173824159216f * 1.4426950408889634f) : 1.0f;
        __half* yp = Yh + (size_t)(rowBase + warp * 16) * 64;
        #pragma unroll
        for (int nb = 0; nb < 8; nb++) {
            int c = nb * 8 + 2 * k4;
            *(uint32_t*)(yp + r4 * 64 + c) =
                pack_h2(acc[nb][0] * sc, acc[nb][1] * sc);
            *(uint32_t*)(yp + (r4 + 8) * 64 + c) =
                pack_h2(acc[nb][2] * sc, acc[nb][3] * sc);
        }
    }
}

// ---------------------------------------------------------------------------
// Flash attention, fp16 m16n8k16. CTA = (128 q-rows, batch); 8 warps x m16;
// KV processed in PAIRS of 64-key tiles (128 keys per epoch): one cp.async
// group + 2 barriers per pair = 1 barrier/tile (was 2). 32 pairs.
// Softmax f16x2; l via tensor core (B = ones), two alternating accumulators.
// ---------------------------------------------------------------------------
#define AQ_STR 72                      // halves
#define AK_STR 72                      // halves (K pair: 128 rows)
#define AVP_STR 136                    // halves (V pair: 64 d-rows x 128 t)
#define A_BIAS 0                       // 4096 halves = 8192 B
#define A_Q    8192                    // 18432 -> 26624
#define A_KP0  26624                   // 128*144 = 18432 -> 45056
#define A_VP0  45056                   // 64*272 = 17408 -> 62464
#define A_KP1  62464                   // -> 80896
#define A_VP1  80896                   // -> 98304
#define A_TOT  98304

__global__ void __launch_bounds__(256, 2) attn_kernel(
    const int* __restrict__ pad_mask, float* __restrict__ out)
{
    extern __shared__ char sm[];
    uint32_t smb = smem_to_u32(sm);

    const int tid = threadIdx.x, lane = tid & 31, warp = tid >> 5;
    const int b = blockIdx.y, qBase = blockIdx.x * 128;
    const int r4 = lane >> 2, k4 = lane & 3;

    const __half* gK  = g_Kh + (size_t)b * TT * 64;
    const __half* gVt = g_Vt + (size_t)b * 64 * TT;
    const int*    pm  = pad_mask + (size_t)b * TT;

    // stage Q tile (fp16, pre-scaled) — its own commit group
    {
        const __half* src = g_Qh + ((size_t)b * TT + qBase) * 64;
        #pragma unroll
        for (int i = 0; i < 4; i++) {
            int idx = tid + i * 256;
            int row = idx >> 3, c = idx & 7;
            cp16(smb + A_Q + row * (AQ_STR * 2) + c * 16, src + row * 64 + c * 8);
        }
        cp_commit();
    }

    // load a PAIR of KV tiles (128 keys) in one commit group
    auto load_pair = [&](int p) {
        int base = p * 128;
        uint32_t kd = smb + ((p & 1) ? A_KP1 : A_KP0);
        uint32_t vd = smb + ((p & 1) ? A_VP1 : A_VP0);
        #pragma unroll
        for (int i = 0; i < 4; i++) {            // K: 128 rows x 8 segs
            int idx = tid + i * 256;
            int row = idx >> 3, c = idx & 7;
            cp16(kd + row * (AK_STR * 2) + c * 16, gK + (size_t)(base + row) * 64 + c * 8);
        }
        #pragma unroll
        for (int i = 0; i < 4; i++) {            // V: 64 d-rows x 16 segs
            int idx = tid + i * 256;
            int d = idx >> 4, c = idx & 15;
            cp16(vd + d * (AVP_STR * 2) + c * 16, gVt + (size_t)d * TT + base + c * 8);
        }
        cp_commit();
    };

    load_pair(0);

    // mask bias as f16 (finite large-negative; exp2 -> exactly 0)
    {
        uint32_t* b16 = (uint32_t*)(sm + A_BIAS);
        for (int i = tid; i < TT / 2; i += 256) {
            int2 m = *(const int2*)(pm + 2 * i);
            b16[i] = (m.x ? 0x0000FBFFu : 0u) | (m.y ? 0xFBFF0000u : 0u);
        }
    }

    cp_wait<1>();        // Q group done (pair0 may still be pending)
    __syncthreads();

    // persistent Q fragments (fp16, 16 u32)
    uint32_t Qr[4][4];
    {
        const __half* Qs = (const __half*)(sm + A_Q);
        int r0 = warp * 16 + r4;
        #pragma unroll
        for (int ks = 0; ks < 4; ks++) {
            int c0 = ks * 16 + 2 * k4;
            Qr[ks][0] = *(const uint32_t*)(Qs + r0 * AQ_STR + c0);
            Qr[ks][1] = *(const uint32_t*)(Qs + (r0 + 8) * AQ_STR + c0);
            Qr[ks][2] = *(const uint32_t*)(Qs + r0 * AQ_STR + c0 + 8);
            Qr[ks][3] = *(const uint32_t*)(Qs + (r0 + 8) * AQ_STR + c0 + 8);
        }
    }

    float o[8][4];
    float la[4] = {0.f, 0.f, 0.f, 0.f};     // row-sum accumulators (via mma),
    float lb[4] = {0.f, 0.f, 0.f, 0.f};     // two to relax the dep chain
    #pragma unroll
    for (int nb = 0; nb < 8; nb++)
        #pragma unroll
        for (int i = 0; i < 4; i++) o[nb][i] = 0.0f;

    const uint32_t ONES = 0x3C003C00u;
    const uint32_t onesb[2] = { ONES, ONES };
    const int NP = TT / 128;                 // 32 pairs

    for (int p = 0; p < NP; p++) {
        if (p > 0) __syncthreads();          // pair p-1 compute done -> reuse OK
        if (p < NP - 1) load_pair(p + 1);
        if (p < NP - 1) cp_wait<1>(); else cp_wait<0>();
        __syncthreads();                     // pair p visible

        const __half* Kp = (const __half*)(sm + ((p & 1) ? A_KP1 : A_KP0));
        const __half* Vp = (const __half*)(sm + ((p & 1) ? A_VP1 : A_VP0));
        const uint32_t* biasp = (const uint32_t*)(sm + A_BIAS) + p * 64;

        #pragma unroll
        for (int h = 0; h < 2; h++) {
            const __half* Ks = Kp + h * 64 * AK_STR;
            const uint32_t* bias16 = biasp + h * 32;

            // ---- S = Q @ K^T (fp16, 4 ksteps of 16) ----
            float s[8][4];
            #pragma unroll
            for (int nb = 0; nb < 8; nb++) {
                s[nb][0] = 0.0f; s[nb][1] = 0.0f; s[nb][2] = 0.0f; s[nb][3] = 0.0f;
            }
            #pragma unroll
            for (int ks = 0; ks < 4; ks++) {
                int c0 = ks * 16 + 2 * k4;
                #pragma unroll
                for (int nb = 0; nb < 8; nb++) {
                    const __half* kk = Ks + (nb * 8 + r4) * AK_STR + c0;
                    uint32_t bb[2] = { *(const uint32_t*)(kk), *(const uint32_t*)(kk + 8) };
                    mma16(s[nb], Qr[ks], bb);
                }
            }

            // ---- softmax in f16x2: p = exp2(s + bias) -> PV A-fragment ----
            uint32_t plo[8], phi[8];
            #pragma unroll
            for (int nb = 0; nb < 8; nb++) {
                uint32_t bv = bias16[nb * 4 + k4];
                plo[nb] = h2exp2(hadd2(pack_h2(s[nb][0], s[nb][1]), bv));
                phi[nb] = h2exp2(hadd2(pack_h2(s[nb][2], s[nb][3]), bv));
            }

            // ---- O += P @ V; l += P @ 1 ----
            #pragma unroll
            for (int nbS = 0; nbS < 4; nbS++) {
                uint32_t a[4] = { plo[2 * nbS], phi[2 * nbS],
                                  plo[2 * nbS + 1], phi[2 * nbS + 1] };
                int sc = h * 64 + nbS * 16 + 2 * k4;
                #pragma unroll
                for (int nb = 0; nb < 8; nb++) {
                    const __half* vp = Vp + (nb * 8 + r4) * AVP_STR + sc;
                    uint32_t bb[2] = { *(const uint32_t*)(vp), *(const uint32_t*)(vp + 8) };
                    mma16(o[nb], a, bb);
                }
                mma16((nbS & 1) ? lb : la, a, onesb);
            }
        }
    }

    // normalize + store (l columns identical within accumulator; rows r4/r4+8)
    float i0 = 1.0f / (la[0] + lb[0]), i1 = 1.0f / (la[2] + lb[2]);

    float* op = out + ((size_t)b * TT + qBase + warp * 16) * 64;
    #pragma unroll
    for (int nb = 0; nb < 8; nb++) {
        int c = nb * 8 + 2 * k4;
        *(float2*)(op + r4 * 64 + c)       = make_float2(o[nb][0] * i0, o[nb][1] * i0);
        *(float2*)(op + (r4 + 8) * 64 + c) = make_float2(o[nb][2] * i1, o[nb][3] * i1);
    }
}

// ---------------------------------------------------------------------------
// kernel_launch: inputs (metadata order): k, v, q, pad_mask, Wk, Wq, Wv
// ---------------------------------------------------------------------------
extern "C" void kernel_launch(void* const* d_in, const int* in_sizes, int n_in,
                              void* d_out, int out_size)
{
    const float* k        = (const float*)d_in[0];
    const float* v        = (const float*)d_in[1];
    const float* q        = (const float*)d_in[2];
    const int*   pad_mask = (const int*)d_in[3];
    const float* Wk       = (const float*)d_in[4];
    const float* Wq       = (const float*)d_in[5];
    const float* Wv       = (const float*)d_in[6];
    float* out = (float*)d_out;

    wconv_kernel<<<24, 256>>>(Wq, Wk, Wv);

    cudaFuncSetAttribute(proj_kernel, cudaFuncAttributeMaxDynamicSharedMemorySize, P_TOT);
    dim3 pg(BB * TT / 128, 3);
    proj_kernel<<<pg, 256, P_TOT>>>(q, k, v);

    cudaFuncSetAttribute(attn_kernel, cudaFuncAttributeMaxDynamicSharedMemorySize, A_TOT);
    dim3 ag(TT / 128, BB);
    attn_kernel<<<ag, 256, A_TOT>>>(pad_mask, out);
}

// round 14
// speedup vs baseline: 1.0706x; 1.0706x over previous
#include <cuda_runtime.h>
#include <cuda_fp16.h>
#include <cstdint>

#define BB 8
#define TT 4096
#define DM 512

// projected Q, K, V scratch (fp16). Q pre-scaled by (1/sqrt(512))*log2(e).
// V stored TRANSPOSED: g_Vt[b][d][t]. g_Wt: W transposed fp16 [which][n][k].
__device__ __align__(256) __half g_Qh[BB * TT * 64];
__device__ __align__(256) __half g_Kh[BB * TT * 64];
__device__ __align__(256) __half g_Vt[BB * 64 * TT];
__device__ __align__(256) __half g_Wt[3 * 64 * DM];

// ---------------------------------------------------------------------------
// helpers
// ---------------------------------------------------------------------------
__device__ __forceinline__ uint32_t smem_to_u32(const void* p) {
    uint32_t a;
    asm("{ .reg .u64 t; cvta.to.shared.u64 t, %1; cvt.u32.u64 %0, t; }" : "=r"(a) : "l"(p));
    return a;
}
__device__ __forceinline__ uint32_t pack_h2(float lo, float hi) {
    uint32_t d; asm("cvt.rn.f16x2.f32 %0, %1, %2;" : "=r"(d) : "f"(hi), "f"(lo)); return d;
}
__device__ __forceinline__ uint32_t hadd2(uint32_t a, uint32_t b) {
    uint32_t d; asm("add.rn.f16x2 %0, %1, %2;" : "=r"(d) : "r"(a), "r"(b)); return d;
}
__device__ __forceinline__ uint32_t h2exp2(uint32_t a) {
    uint32_t d; asm("ex2.approx.f16x2 %0, %1;" : "=r"(d) : "r"(a)); return d;
}
// fp16: D += A(m16 x k16) * B(k16 x n8), f32 accumulate
__device__ __forceinline__ void mma16(float* d, const uint32_t* a, const uint32_t* b) {
    asm volatile(
        "mma.sync.aligned.m16n8k16.row.col.f32.f16.f16.f32 "
        "{%0,%1,%2,%3}, {%4,%5,%6,%7}, {%8,%9}, {%0,%1,%2,%3};"
        : "+f"(d[0]), "+f"(d[1]), "+f"(d[2]), "+f"(d[3])
        : "r"(a[0]), "r"(a[1]), "r"(a[2]), "r"(a[3]), "r"(b[0]), "r"(b[1]));
}
__device__ __forceinline__ void cp16(uint32_t dst, const void* src) {
    asm volatile("cp.async.ca.shared.global [%0], [%1], 16;" :: "r"(dst), "l"(src));
}
__device__ __forceinline__ void cp_commit() { asm volatile("cp.async.commit_group;"); }
template<int N> __device__ __forceinline__ void cp_wait() {
    asm volatile("cp.async.wait_group %0;" :: "n"(N));
}

// ---------------------------------------------------------------------------
// W pre-transpose: g_Wt[which][n][k] = fp16(W[k][n]). 24 blocks.
// ---------------------------------------------------------------------------
__global__ void __launch_bounds__(256) wconv_kernel(
    const float* __restrict__ Wq, const float* __restrict__ Wk,
    const float* __restrict__ Wv)
{
    __shared__ float tile[64][65];
    int which = blockIdx.x >> 3;
    int kb    = (blockIdx.x & 7) * 64;
    const float* W = (which == 0) ? Wq : ((which == 1) ? Wk : Wv);
    __half* Wt = g_Wt + (size_t)which * 64 * DM;
    int tid = threadIdx.x;

    #pragma unroll
    for (int i = 0; i < 16; i++) {
        int idx = tid + i * 256;
        int k = idx >> 6, n = idx & 63;
        tile[k][n] = W[(size_t)(kb + k) * 64 + n];
    }
    __syncthreads();
    #pragma unroll
    for (int i = 0; i < 16; i++) {
        int idx = tid + i * 256;
        int n = idx >> 6, k = idx & 63;
        Wt[(size_t)n * DM + kb + k] = __float2half_rn(tile[k][n]);
    }
}

// ---------------------------------------------------------------------------
// Projection (r12 config): Y[32768,64] = X[32768,512] @ W[512,64], fp16
// m16n8k16, 2-stage double-buffered cp.async pipeline.
// fp16 epilogue: which==0 -> g_Qh (scaled), 1 -> g_Kh, 2 -> g_Vt (transposed).
// ---------------------------------------------------------------------------
#define PX_PAD 36
#define PWT_STR 40
#define P_X0 0
#define P_X1 18432
#define P_W0 36864
#define P_W1 41984
#define P_TOT 47104

__global__ void __launch_bounds__(256, 2) proj_kernel(
    const float* __restrict__ Xq, const float* __restrict__ Xk, const float* __restrict__ Xv)
{
    extern __shared__ char sm[];
    uint32_t smb = smem_to_u32(sm);

    const float* X;
    int which = blockIdx.y;
    if (which == 0)      X = Xq;
    else if (which == 1) X = Xk;
    else                 X = Xv;
    const __half* Wt = g_Wt + (size_t)which * 64 * DM;

    const int tid = threadIdx.x, lane = tid & 31, warp = tid >> 5;
    const int r4 = lane >> 2, k4 = lane & 3;
    const int rowBase = blockIdx.x * 128;

    auto load_chunk = [&](int ch) {
        uint32_t xd = smb + ((ch & 1) ? P_X1 : P_X0);
        uint32_t wd = smb + ((ch & 1) ? P_W1 : P_W0);
        const float* xs = X + (size_t)rowBase * DM + ch * 32;
        #pragma unroll
        for (int i = 0; i < 4; i++) {
            int idx = tid + i * 256;
            int row = idx >> 3, c = idx & 7;
            cp16(xd + row * (PX_PAD * 4) + c * 16, xs + (size_t)row * DM + c * 4);
        }
        {
            int n = tid >> 2, seg = tid & 3;
            cp16(wd + n * (PWT_STR * 2) + seg * 16, Wt + (size_t)n * DM + ch * 32 + seg * 8);
        }
        cp_commit();
    };

    float acc[8][4];
    #pragma unroll
    for (int nb = 0; nb < 8; nb++)
        #pragma unroll
        for (int i = 0; i < 4; i++) acc[nb][i] = 0.0f;

    load_chunk(0);
    for (int ch = 0; ch < 16; ch++) {
        if (ch > 0) __syncthreads();
        if (ch < 15) load_chunk(ch + 1);
        if (ch < 15) cp_wait<1>(); else cp_wait<0>();
        __syncthreads();

        const float*  Xs = (const float*)(sm + ((ch & 1) ? P_X1 : P_X0));
        const __half* Ws = (const __half*)(sm + ((ch & 1) ? P_W1 : P_W0));

        #pragma unroll
        for (int ks = 0; ks < 2; ks++) {
            int c0 = ks * 16 + 2 * k4;
            const float* xp  = Xs + (warp * 16 + r4) * PX_PAD + c0;
            const float* xp8 = xp + 8 * PX_PAD;
            uint32_t a[4] = {
                pack_h2(xp[0],  xp[1]),
                pack_h2(xp8[0], xp8[1]),
                pack_h2(xp[8],  xp[9]),
                pack_h2(xp8[8], xp8[9])
            };
            #pragma unroll
            for (int nb = 0; nb < 8; nb++) {
                const __half* wn = Ws + (nb * 8 + r4) * PWT_STR + c0;
                uint32_t bb[2] = { *(const uint32_t*)(wn), *(const uint32_t*)(wn + 8) };
                mma16(acc[nb], a, bb);
            }
        }
    }

    if (which == 2) {
        int m = rowBase + warp * 16 + r4;
        int bq = m >> 12;
        int t = m & 4095;
        #pragma unroll
        for (int nb = 0; nb < 8; nb++) {
            int d = nb * 8 + 2 * k4;
            g_Vt[((size_t)bq * 64 + d)     * TT + t]     = __float2half_rn(acc[nb][0]);
            g_Vt[((size_t)bq * 64 + d + 1) * TT + t]     = __float2half_rn(acc[nb][1]);
            g_Vt[((size_t)bq * 64 + d)     * TT + t + 8] = __float2half_rn(acc[nb][2]);
            g_Vt[((size_t)bq * 64 + d + 1) * TT + t + 8] = __float2half_rn(acc[nb][3]);
        }
    } else {
        __half* Yh = (which == 0) ? g_Qh : g_Kh;
        const float sc = (which == 0)
            ? (0.044194173824159216f * 1.4426950408889634f) : 1.0f;
        __half* yp = Yh + (size_t)(rowBase + warp * 16) * 64;
        #pragma unroll
        for (int nb = 0; nb < 8; nb++) {
            int c = nb * 8 + 2 * k4;
            *(uint32_t*)(yp + r4 * 64 + c) =
                pack_h2(acc[nb][0] * sc, acc[nb][1] * sc);
            *(uint32_t*)(yp + (r4 + 8) * 64 + c) =
                pack_h2(acc[nb][2] * sc, acc[nb][3] * sc);
        }
    }
}

// ---------------------------------------------------------------------------
// Flash attention, fp16 m16n8k16. CTA = (128 q-rows, batch); 4 warps, each
// warp m32 x n64 (K/V fragments reused across BOTH m16 halves -> smem reads
// halved vs m16 warps). 128 threads, big register budget (LB 128,2).
// Bc=64, 64 tiles; 2 CTAs/SM; grid 256 = single wave.
// Softmax f16x2; l via tensor core (B = ones), per-m2 accumulators.
// ---------------------------------------------------------------------------
#define AQ_STR 72                      // halves
#define AK_STR 72
#define AV_STR 72
#define A_BIAS 0                       // 2048 u32 = 8192 B
#define A_Q    8192                    // 128*144 = 18432 -> 26624
#define A_K0   26624                   // 64*144 = 9216 -> 35840
#define A_K1   35840                   // -> 45056
#define A_V0   45056                   // -> 54272
#define A_V1   54272                   // -> 63488
#define A_TOT  63488

__global__ void __launch_bounds__(128, 2) attn_kernel(
    const int* __restrict__ pad_mask, float* __restrict__ out)
{
    extern __shared__ char sm[];
    uint32_t smb = smem_to_u32(sm);

    const int tid = threadIdx.x, lane = tid & 31, warp = tid >> 5;   // warp 0..3
    const int b = blockIdx.y, qBase = blockIdx.x * 128;
    const int r4 = lane >> 2, k4 = lane & 3;

    const __half* gK  = g_Kh + (size_t)b * TT * 64;
    const __half* gVt = g_Vt + (size_t)b * 64 * TT;
    const int*    pm  = pad_mask + (size_t)b * TT;

    // stage Q tile (fp16, pre-scaled) — its own commit group
    {
        const __half* src = g_Qh + ((size_t)b * TT + qBase) * 64;
        #pragma unroll
        for (int i = 0; i < 8; i++) {
            int idx = tid + i * 128;
            int row = idx >> 3, c = idx & 7;
            cp16(smb + A_Q + row * (AQ_STR * 2) + c * 16, src + row * 64 + c * 8);
        }
        cp_commit();
    }

    auto load_tile = [&](int t) {
        int base = t * 64;
        uint32_t kd = smb + ((t & 1) ? A_K1 : A_K0);
        uint32_t vd = smb + ((t & 1) ? A_V1 : A_V0);
        #pragma unroll
        for (int i = 0; i < 4; i++) {
            int idx = tid + i * 128;
            int row = idx >> 3, c = idx & 7;
            cp16(kd + row * (AK_STR * 2) + c * 16, gK + (size_t)(base + row) * 64 + c * 8);
        }
        #pragma unroll
        for (int i = 0; i < 4; i++) {
            int idx = tid + i * 128;
            int d = idx >> 3, c = idx & 7;
            cp16(vd + d * (AV_STR * 2) + c * 16, gVt + (size_t)d * TT + base + c * 8);
        }
        cp_commit();
    };

    load_tile(0);

    // mask bias as f16 (finite large-negative; exp2 -> exactly 0)
    {
        uint32_t* b16 = (uint32_t*)(sm + A_BIAS);
        for (int i = tid; i < TT / 2; i += 128) {
            int2 m = *(const int2*)(pm + 2 * i);
            b16[i] = (m.x ? 0x0000FBFFu : 0u) | (m.y ? 0xFBFF0000u : 0u);
        }
    }

    cp_wait<1>();        // Q group done (tile0 may still be pending)
    __syncthreads();

    // persistent Q fragments: 2 m16-blocks (rows warp*32 .. +31), fp16
    uint32_t Qr[2][4][4];
    {
        const __half* Qs = (const __half*)(sm + A_Q);
        #pragma unroll
        for (int m2 = 0; m2 < 2; m2++) {
            int r0 = warp * 32 + m2 * 16 + r4;
            #pragma unroll
            for (int ks = 0; ks < 4; ks++) {
                int c0 = ks * 16 + 2 * k4;
                Qr[m2][ks][0] = *(const uint32_t*)(Qs + r0 * AQ_STR + c0);
                Qr[m2][ks][1] = *(const uint32_t*)(Qs + (r0 + 8) * AQ_STR + c0);
                Qr[m2][ks][2] = *(const uint32_t*)(Qs + r0 * AQ_STR + c0 + 8);
                Qr[m2][ks][3] = *(const uint32_t*)(Qs + (r0 + 8) * AQ_STR + c0 + 8);
            }
        }
    }

    float o[2][8][4];
    float la[4] = {0.f, 0.f, 0.f, 0.f};     // row-sum (m2=0) via mma
    float lb[4] = {0.f, 0.f, 0.f, 0.f};     // row-sum (m2=1) via mma
    #pragma unroll
    for (int m2 = 0; m2 < 2; m2++)
        #pragma unroll
        for (int nb = 0; nb < 8; nb++)
            #pragma unroll
            for (int i = 0; i < 4; i++) o[m2][nb][i] = 0.0f;

    const uint32_t ONES = 0x3C003C00u;
    const uint32_t onesb[2] = { ONES, ONES };
    const int NT = TT / 64;

    for (int t = 0; t < NT; t++) {
        if (t > 0) __syncthreads();          // compute t-1 done -> buffer reuse OK
        if (t < NT - 1) load_tile(t + 1);
        if (t < NT - 1) cp_wait<1>(); else cp_wait<0>();
        __syncthreads();

        const __half* Ks = (const __half*)(sm + ((t & 1) ? A_K1 : A_K0));
        const __half* Vs = (const __half*)(sm + ((t & 1) ? A_V1 : A_V0));
        const uint32_t* bias16 = (const uint32_t*)(sm + A_BIAS) + t * 32;

        // ---- S = Q @ K^T (fp16): each K B-frag feeds BOTH m16 halves ----
        float s[2][8][4];
        #pragma unroll
        for (int m2 = 0; m2 < 2; m2++)
            #pragma unroll
            for (int nb = 0; nb < 8; nb++) {
                s[m2][nb][0] = 0.0f; s[m2][nb][1] = 0.0f;
                s[m2][nb][2] = 0.0f; s[m2][nb][3] = 0.0f;
            }
        #pragma unroll
        for (int ks = 0; ks < 4; ks++) {
            int c0 = ks * 16 + 2 * k4;
            #pragma unroll
            for (int nb = 0; nb < 8; nb++) {
                const __half* kk = Ks + (nb * 8 + r4) * AK_STR + c0;
                uint32_t bb[2] = { *(const uint32_t*)(kk), *(const uint32_t*)(kk + 8) };
                mma16(s[0][nb], Qr[0][ks], bb);
                mma16(s[1][nb], Qr[1][ks], bb);
            }
        }

        // ---- softmax in f16x2: p = exp2(s + bias) -> PV A-fragments ----
        uint32_t plo[2][8], phi[2][8];
        #pragma unroll
        for (int nb = 0; nb < 8; nb++) {
            uint32_t bv = bias16[nb * 4 + k4];
            #pragma unroll
            for (int m2 = 0; m2 < 2; m2++) {
                plo[m2][nb] = h2exp2(hadd2(pack_h2(s[m2][nb][0], s[m2][nb][1]), bv));
                phi[m2][nb] = h2exp2(hadd2(pack_h2(s[m2][nb][2], s[m2][nb][3]), bv));
            }
        }

        // ---- O += P @ V; l += P @ 1. V B-frags feed BOTH m16 halves ----
        #pragma unroll
        for (int nbS = 0; nbS < 4; nbS++) {
            uint32_t a0[4] = { plo[0][2 * nbS], phi[0][2 * nbS],
                               plo[0][2 * nbS + 1], phi[0][2 * nbS + 1] };
            uint32_t a1[4] = { plo[1][2 * nbS], phi[1][2 * nbS],
                               plo[1][2 * nbS + 1], phi[1][2 * nbS + 1] };
            int sc = nbS * 16 + 2 * k4;
            #pragma unroll
            for (int nb = 0; nb < 8; nb++) {
                const __half* vp = Vs + (nb * 8 + r4) * AV_STR + sc;
                uint32_t bb[2] = { *(const uint32_t*)(vp), *(const uint32_t*)(vp + 8) };
                mma16(o[0][nb], a0, bb);
                mma16(o[1][nb], a1, bb);
            }
            mma16(la, a0, onesb);
            mma16(lb, a1, onesb);
        }
    }

    // normalize + store: m2=0 uses la, m2=1 uses lb; rows r4 / r4+8
    float inv[2][2];
    inv[0][0] = 1.0f / la[0]; inv[0][1] = 1.0f / la[2];
    inv[1][0] = 1.0f / lb[0]; inv[1][1] = 1.0f / lb[2];

    #pragma unroll
    for (int m2 = 0; m2 < 2; m2++) {
        float* op = out + ((size_t)b * TT + qBase + warp * 32 + m2 * 16) * 64;
        #pragma unroll
        for (int nb = 0; nb < 8; nb++) {
            int c = nb * 8 + 2 * k4;
            *(float2*)(op + r4 * 64 + c) =
                make_float2(o[m2][nb][0] * inv[m2][0], o[m2][nb][1] * inv[m2][0]);
            *(float2*)(op + (r4 + 8) * 64 + c) =
                make_float2(o[m2][nb][2] * inv[m2][1], o[m2][nb][3] * inv[m2][1]);
        }
    }
}

// ---------------------------------------------------------------------------
// kernel_launch: inputs (metadata order): k, v, q, pad_mask, Wk, Wq, Wv
// ---------------------------------------------------------------------------
extern "C" void kernel_launch(void* const* d_in, const int* in_sizes, int n_in,
                              void* d_out, int out_size)
{
    const float* k        = (const float*)d_in[0];
    const float* v        = (const float*)d_in[1];
    const float* q        = (const float*)d_in[2];
    const int*   pad_mask = (const int*)d_in[3];
    const float* Wk       = (const float*)d_in[4];
    const float* Wq       = (const float*)d_in[5];
    const float* Wv       = (const float*)d_in[6];
    float* out = (float*)d_out;

    wconv_kernel<<<24, 256>>>(Wq, Wk, Wv);

    cudaFuncSetAttribute(proj_kernel, cudaFuncAttributeMaxDynamicSharedMemorySize, P_TOT);
    dim3 pg(BB * TT / 128, 3);
    proj_kernel<<<pg, 256, P_TOT>>>(q, k, v);

    cudaFuncSetAttribute(attn_kernel, cudaFuncAttributeMaxDynamicSharedMemorySize, A_TOT);
    dim3 ag(TT / 128, BB);
    attn_kernel<<<ag, 128, A_TOT>>>(pad_mask, out);
}

// round 15
// speedup vs baseline: 1.4773x; 1.3799x over previous
#include <cuda_runtime.h>
#include <cuda_fp16.h>
#include <cstdint>

#define BB 8
#define TT 4096
#define DM 512

// fp16 scratch. Q pre-scaled by (1/sqrt(512))*log2(e). K/V are written
// COMPACTED over valid (unmasked) key positions; V also TRANSPOSED [b][d][j].
__device__ __align__(256) __half g_Qh[BB * TT * 64];
__device__ __align__(256) __half g_Kc[BB * TT * 64];
__device__ __align__(256) __half g_Vtc[BB * 64 * TT];
__device__ __align__(256) __half g_Wt[3 * 64 * DM];
__device__ int      g_slot[BB * TT];      // valid -> compact idx, masked -> -1
__device__ int      g_nt[BB];             // ceil(nvalid/64)
__device__ uint32_t g_biasc[BB * TT / 2]; // compacted f16x2 bias (tail = -64k)

// ---------------------------------------------------------------------------
// helpers
// ---------------------------------------------------------------------------
__device__ __forceinline__ uint32_t smem_to_u32(const void* p) {
    uint32_t a;
    asm("{ .reg .u64 t; cvta.to.shared.u64 t, %1; cvt.u32.u64 %0, t; }" : "=r"(a) : "l"(p));
    return a;
}
__device__ __forceinline__ uint32_t pack_h2(float lo, float hi) {
    uint32_t d; asm("cvt.rn.f16x2.f32 %0, %1, %2;" : "=r"(d) : "f"(hi), "f"(lo)); return d;
}
__device__ __forceinline__ uint32_t hadd2(uint32_t a, uint32_t b) {
    uint32_t d; asm("add.rn.f16x2 %0, %1, %2;" : "=r"(d) : "r"(a), "r"(b)); return d;
}
__device__ __forceinline__ uint32_t h2exp2(uint32_t a) {
    uint32_t d; asm("ex2.approx.f16x2 %0, %1;" : "=r"(d) : "r"(a)); return d;
}
// fp16: D += A(m16 x k16) * B(k16 x n8), f32 accumulate
__device__ __forceinline__ void mma16(float* d, const uint32_t* a, const uint32_t* b) {
    asm volatile(
        "mma.sync.aligned.m16n8k16.row.col.f32.f16.f16.f32 "
        "{%0,%1,%2,%3}, {%4,%5,%6,%7}, {%8,%9}, {%0,%1,%2,%3};"
        : "+f"(d[0]), "+f"(d[1]), "+f"(d[2]), "+f"(d[3])
        : "r"(a[0]), "r"(a[1]), "r"(a[2]), "r"(a[3]), "r"(b[0]), "r"(b[1]));
}
__device__ __forceinline__ void cp16(uint32_t dst, const void* src) {
    asm volatile("cp.async.ca.shared.global [%0], [%1], 16;" :: "r"(dst), "l"(src));
}
__device__ __forceinline__ void cp_commit() { asm volatile("cp.async.commit_group;"); }
template<int N> __device__ __forceinline__ void cp_wait() {
    asm volatile("cp.async.wait_group %0;" :: "n"(N));
}

// ---------------------------------------------------------------------------
// W pre-transpose: g_Wt[which][n][k] = fp16(W[k][n]). 24 blocks.
// ---------------------------------------------------------------------------
__global__ void __launch_bounds__(256) wconv_kernel(
    const float* __restrict__ Wq, const float* __restrict__ Wk,
    const float* __restrict__ Wv)
{
    __shared__ float tile[64][65];
    int which = blockIdx.x >> 3;
    int kb    = (blockIdx.x & 7) * 64;
    const float* W = (which == 0) ? Wq : ((which == 1) ? Wk : Wv);
    __half* Wt = g_Wt + (size_t)which * 64 * DM;
    int tid = threadIdx.x;

    #pragma unroll
    for (int i = 0; i < 16; i++) {
        int idx = tid + i * 256;
        int k = idx >> 6, n = idx & 63;
        tile[k][n] = W[(size_t)(kb + k) * 64 + n];
    }
    __syncthreads();
    #pragma unroll
    for (int i = 0; i < 16; i++) {
        int idx = tid + i * 256;
        int n = idx >> 6, k = idx & 63;
        Wt[(size_t)n * DM + kb + k] = __float2half_rn(tile[k][n]);
    }
}

// ---------------------------------------------------------------------------
// Key compaction scan: per batch, prefix-sum the valid (pad_mask==0) keys.
// Writes g_slot (dest index or -1), g_nt, compacted bias, zeroes K/V pads.
// ---------------------------------------------------------------------------
__global__ void __launch_bounds__(256) scan_kernel(const int* __restrict__ pm_g)
{
    int b = blockIdx.x;
    const int* m = pm_g + (size_t)b * TT;
    int tid = threadIdx.x;
    int base = tid * 16;

    int v[16];
    int cnt = 0;
    #pragma unroll
    for (int i = 0; i < 16; i += 4) {
        int4 mm = *(const int4*)(m + base + i);
        v[i] = (mm.x == 0); v[i + 1] = (mm.y == 0);
        v[i + 2] = (mm.z == 0); v[i + 3] = (mm.w == 0);
        cnt += v[i] + v[i + 1] + v[i + 2] + v[i + 3];
    }

    __shared__ int ssum[256];
    ssum[tid] = cnt;
    __syncthreads();
    for (int off = 1; off < 256; off <<= 1) {
        int t = (tid >= off) ? ssum[tid - off] : 0;
        __syncthreads();
        ssum[tid] += t;
        __syncthreads();
    }
    int total = ssum[255];
    int o = ssum[tid] - cnt;   // exclusive prefix

    int* slot = g_slot + (size_t)b * TT;
    #pragma unroll
    for (int i = 0; i < 16; i++) {
        slot[base + i] = v[i] ? o : -1;
        o += v[i];
    }

    int nt = (total + 63) >> 6;
    if (tid == 0) g_nt[b] = nt;
    int padEnd = nt * 64;

    // compacted bias pairs: 0 for valid, -64k (0xFBFF) for tail pads
    uint32_t* bc = g_biasc + (size_t)b * (TT / 2);
    for (int j2 = tid; j2 < (padEnd >> 1); j2 += 256) {
        int j0 = 2 * j2;
        uint32_t w = 0;
        if (j0 >= total)     w |= 0x0000FBFFu;
        if (j0 + 1 >= total) w |= 0xFBFF0000u;
        bc[j2] = w;
    }

    // zero K pad rows
    for (int j = total + tid; j < padEnd; j += 256) {
        uint32_t* kr = (uint32_t*)(g_Kc + ((size_t)b * TT + j) * 64);
        #pragma unroll
        for (int c = 0; c < 32; c++) kr[c] = 0;
    }
    // zero Vt pad columns
    int P = padEnd - total;
    if (P > 0) {
        for (int x = tid; x < P * 64; x += 256) {
            int d = x / P, j = total + x % P;
            g_Vtc[((size_t)b * 64 + d) * TT + j] = __ushort_as_half((unsigned short)0);
        }
    }
}

// ---------------------------------------------------------------------------
// Projection: Y[32768,64] = X[32768,512] @ W[512,64], fp16 m16n8k16,
// 2-stage double-buffered cp.async pipeline.
// Epilogue: which==0 -> g_Qh (scaled, full); which==1 -> g_Kc (compacted via
// g_slot); which==2 -> g_Vtc (compacted + transposed). Masked rows skipped.
// ---------------------------------------------------------------------------
#define PX_PAD 36
#define PWT_STR 40
#define P_X0 0
#define P_X1 18432
#define P_W0 36864
#define P_W1 41984
#define P_TOT 47104

__global__ void __launch_bounds__(256, 2) proj_kernel(
    const float* __restrict__ Xq, const float* __restrict__ Xk, const float* __restrict__ Xv)
{
    extern __shared__ char sm[];
    uint32_t smb = smem_to_u32(sm);

    const float* X;
    int which = blockIdx.y;
    if (which == 0)      X = Xq;
    else if (which == 1) X = Xk;
    else                 X = Xv;
    const __half* Wt = g_Wt + (size_t)which * 64 * DM;

    const int tid = threadIdx.x, lane = tid & 31, warp = tid >> 5;
    const int r4 = lane >> 2, k4 = lane & 3;
    const int rowBase = blockIdx.x * 128;

    auto load_chunk = [&](int ch) {
        uint32_t xd = smb + ((ch & 1) ? P_X1 : P_X0);
        uint32_t wd = smb + ((ch & 1) ? P_W1 : P_W0);
        const float* xs = X + (size_t)rowBase * DM + ch * 32;
        #pragma unroll
        for (int i = 0; i < 4; i++) {
            int idx = tid + i * 256;
            int row = idx >> 3, c = idx & 7;
            cp16(xd + row * (PX_PAD * 4) + c * 16, xs + (size_t)row * DM + c * 4);
        }
        {
            int n = tid >> 2, seg = tid & 3;
            cp16(wd + n * (PWT_STR * 2) + seg * 16, Wt + (size_t)n * DM + ch * 32 + seg * 8);
        }
        cp_commit();
    };

    float acc[8][4];
    #pragma unroll
    for (int nb = 0; nb < 8; nb++)
        #pragma unroll
        for (int i = 0; i < 4; i++) acc[nb][i] = 0.0f;

    load_chunk(0);
    for (int ch = 0; ch < 16; ch++) {
        if (ch > 0) __syncthreads();
        if (ch < 15) load_chunk(ch + 1);
        if (ch < 15) cp_wait<1>(); else cp_wait<0>();
        __syncthreads();

        const float*  Xs = (const float*)(sm + ((ch & 1) ? P_X1 : P_X0));
        const __half* Ws = (const __half*)(sm + ((ch & 1) ? P_W1 : P_W0));

        #pragma unroll
        for (int ks = 0; ks < 2; ks++) {
            int c0 = ks * 16 + 2 * k4;
            const float* xp  = Xs + (warp * 16 + r4) * PX_PAD + c0;
            const float* xp8 = xp + 8 * PX_PAD;
            uint32_t a[4] = {
                pack_h2(xp[0],  xp[1]),
                pack_h2(xp8[0], xp8[1]),
                pack_h2(xp[8],  xp[9]),
                pack_h2(xp8[8], xp8[9])
            };
            #pragma unroll
            for (int nb = 0; nb < 8; nb++) {
                const __half* wn = Ws + (nb * 8 + r4) * PWT_STR + c0;
                uint32_t bb[2] = { *(const uint32_t*)(wn), *(const uint32_t*)(wn + 8) };
                mma16(acc[nb], a, bb);
            }
        }
    }

    // epilogue
    int m0 = rowBase + warp * 16 + r4;      // first row; second is m0+8
    if (which == 0) {
        const float sc = 0.044194173824159216f * 1.4426950408889634f;
        __half* yp = g_Qh + (size_t)m0 * 64;
        #pragma unroll
        for (int nb = 0; nb < 8; nb++) {
            int c = nb * 8 + 2 * k4;
            *(uint32_t*)(yp + c)          = pack_h2(acc[nb][0] * sc, acc[nb][1] * sc);
            *(uint32_t*)(yp + 8 * 64 + c) = pack_h2(acc[nb][2] * sc, acc[nb][3] * sc);
        }
    } else {
        int bq = m0 >> 12;
        int t0 = m0 & 4095;
        int s0 = g_slot[(size_t)bq * TT + t0];
        int s1 = g_slot[(size_t)bq * TT + t0 + 8];
        if (which == 1) {
            __half* y0 = g_Kc + ((size_t)bq * TT + s0) * 64;
            __half* y1 = g_Kc + ((size_t)bq * TT + s1) * 64;
            #pragma unroll
            for (int nb = 0; nb < 8; nb++) {
                int c = nb * 8 + 2 * k4;
                if (s0 >= 0) *(uint32_t*)(y0 + c) = pack_h2(acc[nb][0], acc[nb][1]);
                if (s1 >= 0) *(uint32_t*)(y1 + c) = pack_h2(acc[nb][2], acc[nb][3]);
            }
        } else {
            __half* vb = g_Vtc + (size_t)bq * 64 * TT;
            #pragma unroll
            for (int nb = 0; nb < 8; nb++) {
                int d = nb * 8 + 2 * k4;
                if (s0 >= 0) {
                    vb[(size_t)d * TT + s0]       = __float2half_rn(acc[nb][0]);
                    vb[(size_t)(d + 1) * TT + s0] = __float2half_rn(acc[nb][1]);
                }
                if (s1 >= 0) {
                    vb[(size_t)d * TT + s1]       = __float2half_rn(acc[nb][2]);
                    vb[(size_t)(d + 1) * TT + s1] = __float2half_rn(acc[nb][3]);
                }
            }
        }
    }
}

// ---------------------------------------------------------------------------
// Flash attention over COMPACTED keys, fp16 m16n8k16. CTA = (128 q-rows,
// batch); 4 warps x m32 x n64; dynamic tile count g_nt[b] (~32); 2 CTAs/SM.
// Softmax f16x2 with compacted bias (valid=0, pads=-64k); l via tensor core.
// ---------------------------------------------------------------------------
#define AQ_STR 72
#define AK_STR 72
#define AV_STR 72
#define A_BIAS 0                       // 2048 u32 = 8192 B
#define A_Q    8192
#define A_K0   26624
#define A_K1   35840
#define A_V0   45056
#define A_V1   54272
#define A_TOT  63488

__global__ void __launch_bounds__(128, 2) attn_kernel(float* __restrict__ out)
{
    extern __shared__ char sm[];
    uint32_t smb = smem_to_u32(sm);

    const int tid = threadIdx.x, lane = tid & 31, warp = tid >> 5;
    const int b = blockIdx.y, qBase = blockIdx.x * 128;
    const int r4 = lane >> 2, k4 = lane & 3;

    const __half* gK  = g_Kc  + (size_t)b * TT * 64;
    const __half* gVt = g_Vtc + (size_t)b * 64 * TT;
    const int nt = g_nt[b];

    // stage Q tile (fp16, pre-scaled) — its own commit group
    {
        const __half* src = g_Qh + ((size_t)b * TT + qBase) * 64;
        #pragma unroll
        for (int i = 0; i < 8; i++) {
            int idx = tid + i * 128;
            int row = idx >> 3, c = idx & 7;
            cp16(smb + A_Q + row * (AQ_STR * 2) + c * 16, src + row * 64 + c * 8);
        }
        cp_commit();
    }

    auto load_tile = [&](int t) {
        int base = t * 64;
        uint32_t kd = smb + ((t & 1) ? A_K1 : A_K0);
        uint32_t vd = smb + ((t & 1) ? A_V1 : A_V0);
        #pragma unroll
        for (int i = 0; i < 4; i++) {
            int idx = tid + i * 128;
            int row = idx >> 3, c = idx & 7;
            cp16(kd + row * (AK_STR * 2) + c * 16, gK + (size_t)(base + row) * 64 + c * 8);
        }
        #pragma unroll
        for (int i = 0; i < 4; i++) {
            int idx = tid + i * 128;
            int d = idx >> 3, c = idx & 7;
            cp16(vd + d * (AV_STR * 2) + c * 16, gVt + (size_t)d * TT + base + c * 8);
        }
        cp_commit();
    };

    load_tile(0);

    // stage compacted bias (nt*32 u32)
    {
        uint32_t* b16 = (uint32_t*)(sm + A_BIAS);
        const uint32_t* src = g_biasc + (size_t)b * (TT / 2);
        for (int i = tid; i < nt * 32; i += 128) b16[i] = src[i];
    }

    cp_wait<1>();
    __syncthreads();

    // persistent Q fragments: 2 m16-blocks (rows warp*32 .. +31)
    uint32_t Qr[2][4][4];
    {
        const __half* Qs = (const __half*)(sm + A_Q);
        #pragma unroll
        for (int m2 = 0; m2 < 2; m2++) {
            int r0 = warp * 32 + m2 * 16 + r4;
            #pragma unroll
            for (int ks = 0; ks < 4; ks++) {
                int c0 = ks * 16 + 2 * k4;
                Qr[m2][ks][0] = *(const uint32_t*)(Qs + r0 * AQ_STR + c0);
                Qr[m2][ks][1] = *(const uint32_t*)(Qs + (r0 + 8) * AQ_STR + c0);
                Qr[m2][ks][2] = *(const uint32_t*)(Qs + r0 * AQ_STR + c0 + 8);
                Qr[m2][ks][3] = *(const uint32_t*)(Qs + (r0 + 8) * AQ_STR + c0 + 8);
            }
        }
    }

    float o[2][8][4];
    float la[4] = {0.f, 0.f, 0.f, 0.f};
    float lb[4] = {0.f, 0.f, 0.f, 0.f};
    #pragma unroll
    for (int m2 = 0; m2 < 2; m2++)
        #pragma unroll
        for (int nb = 0; nb < 8; nb++)
            #pragma unroll
            for (int i = 0; i < 4; i++) o[m2][nb][i] = 0.0f;

    const uint32_t ONES = 0x3C003C00u;
    const uint32_t onesb[2] = { ONES, ONES };

    for (int t = 0; t < nt; t++) {
        if (t > 0) __syncthreads();
        if (t < nt - 1) load_tile(t + 1);
        if (t < nt - 1) cp_wait<1>(); else cp_wait<0>();
        __syncthreads();

        const __half* Ks = (const __half*)(sm + ((t & 1) ? A_K1 : A_K0));
        const __half* Vs = (const __half*)(sm + ((t & 1) ? A_V1 : A_V0));
        const uint32_t* bias16 = (const uint32_t*)(sm + A_BIAS) + t * 32;

        // ---- S = Q @ K^T: each K B-frag feeds BOTH m16 halves ----
        float s[2][8][4];
        #pragma unroll
        for (int m2 = 0; m2 < 2; m2++)
            #pragma unroll
            for (int nb = 0; nb < 8; nb++) {
                s[m2][nb][0] = 0.0f; s[m2][nb][1] = 0.0f;
                s[m2][nb][2] = 0.0f; s[m2][nb][3] = 0.0f;
            }
        #pragma unroll
        for (int ks = 0; ks < 4; ks++) {
            int c0 = ks * 16 + 2 * k4;
            #pragma unroll
            for (int nb = 0; nb < 8; nb++) {
                const __half* kk = Ks + (nb * 8 + r4) * AK_STR + c0;
                uint32_t bb[2] = { *(const uint32_t*)(kk), *(const uint32_t*)(kk + 8) };
                mma16(s[0][nb], Qr[0][ks], bb);
                mma16(s[1][nb], Qr[1][ks], bb);
            }
        }

        // ---- softmax in f16x2 ----
        uint32_t plo[2][8], phi[2][8];
        #pragma unroll
        for (int nb = 0; nb < 8; nb++) {
            uint32_t bv = bias16[nb * 4 + k4];
            #pragma unroll
            for (int m2 = 0; m2 < 2; m2++) {
                plo[m2][nb] = h2exp2(hadd2(pack_h2(s[m2][nb][0], s[m2][nb][1]), bv));
                phi[m2][nb] = h2exp2(hadd2(pack_h2(s[m2][nb][2], s[m2][nb][3]), bv));
            }
        }

        // ---- O += P @ V; l += P @ 1 ----
        #pragma unroll
        for (int nbS = 0; nbS < 4; nbS++) {
            uint32_t a0[4] = { plo[0][2 * nbS], phi[0][2 * nbS],
                               plo[0][2 * nbS + 1], phi[0][2 * nbS + 1] };
            uint32_t a1[4] = { plo[1][2 * nbS], phi[1][2 * nbS],
                               plo[1][2 * nbS + 1], phi[1][2 * nbS + 1] };
            int sc = nbS * 16 + 2 * k4;
            #pragma unroll
            for (int nb = 0; nb < 8; nb++) {
                const __half* vp = Vs + (nb * 8 + r4) * AV_STR + sc;
                uint32_t bb[2] = { *(const uint32_t*)(vp), *(const uint32_t*)(vp + 8) };
                mma16(o[0][nb], a0, bb);
                mma16(o[1][nb], a1, bb);
            }
            mma16(la, a0, onesb);
            mma16(lb, a1, onesb);
        }
    }

    float inv[2][2];
    inv[0][0] = 1.0f / la[0]; inv[0][1] = 1.0f / la[2];
    inv[1][0] = 1.0f / lb[0]; inv[1][1] = 1.0f / lb[2];

    #pragma unroll
    for (int m2 = 0; m2 < 2; m2++) {
        float* op = out + ((size_t)b * TT + qBase + warp * 32 + m2 * 16) * 64;
        #pragma unroll
        for (int nb = 0; nb < 8; nb++) {
            int c = nb * 8 + 2 * k4;
            *(float2*)(op + r4 * 64 + c) =
                make_float2(o[m2][nb][0] * inv[m2][0], o[m2][nb][1] * inv[m2][0]);
            *(float2*)(op + (r4 + 8) * 64 + c) =
                make_float2(o[m2][nb][2] * inv[m2][1], o[m2][nb][3] * inv[m2][1]);
        }
    }
}

// ---------------------------------------------------------------------------
// kernel_launch: inputs (metadata order): k, v, q, pad_mask, Wk, Wq, Wv
// ---------------------------------------------------------------------------
extern "C" void kernel_launch(void* const* d_in, const int* in_sizes, int n_in,
                              void* d_out, int out_size)
{
    const float* k        = (const float*)d_in[0];
    const float* v        = (const float*)d_in[1];
    const float* q        = (const float*)d_in[2];
    const int*   pad_mask = (const int*)d_in[3];
    const float* Wk       = (const float*)d_in[4];
    const float* Wq       = (const float*)d_in[5];
    const float* Wv       = (const float*)d_in[6];
    float* out = (float*)d_out;

    wconv_kernel<<<24, 256>>>(Wq, Wk, Wv);
    scan_kernel<<<BB, 256>>>(pad_mask);

    cudaFuncSetAttribute(proj_kernel, cudaFuncAttributeMaxDynamicSharedMemorySize, P_TOT);
    dim3 pg(BB * TT / 128, 3);
    proj_kernel<<<pg, 256, P_TOT>>>(q, k, v);

    cudaFuncSetAttribute(attn_kernel, cudaFuncAttributeMaxDynamicSharedMemorySize, A_TOT);
    dim3 ag(TT / 128, BB);
    attn_kernel<<<ag, 128, A_TOT>>>(out);
}

// round 16
// speedup vs baseline: 1.7468x; 1.1824x over previous
#include <cuda_runtime.h>
#include <cuda_fp16.h>
#include <cstdint>

#define BB 8
#define TT 4096
#define DM 512

// fp16 scratch. Q pre-scaled by (1/sqrt(512))*log2(e). K/V are written
// COMPACTED over valid (unmasked) key positions; V also TRANSPOSED [b][d][j].
__device__ __align__(256) __half g_Qh[BB * TT * 64];
__device__ __align__(256) __half g_Kc[BB * TT * 64];
__device__ __align__(256) __half g_Vtc[BB * 64 * TT];
__device__ __align__(256) __half g_Wt[3 * 64 * DM];
__device__ int      g_tidx[BB * TT];      // compact j -> original t (tail = 0)
__device__ int      g_total[BB];          // valid count
__device__ int      g_nt[BB];             // ceil(valid/64)
__device__ uint32_t g_biasc[BB * TT / 2]; // compacted f16x2 bias (tail = -64k)

// ---------------------------------------------------------------------------
// helpers
// ---------------------------------------------------------------------------
__device__ __forceinline__ uint32_t smem_to_u32(const void* p) {
    uint32_t a;
    asm("{ .reg .u64 t; cvta.to.shared.u64 t, %1; cvt.u32.u64 %0, t; }" : "=r"(a) : "l"(p));
    return a;
}
__device__ __forceinline__ uint32_t pack_h2(float lo, float hi) {
    uint32_t d; asm("cvt.rn.f16x2.f32 %0, %1, %2;" : "=r"(d) : "f"(hi), "f"(lo)); return d;
}
__device__ __forceinline__ uint32_t hadd2(uint32_t a, uint32_t b) {
    uint32_t d; asm("add.rn.f16x2 %0, %1, %2;" : "=r"(d) : "r"(a), "r"(b)); return d;
}
__device__ __forceinline__ uint32_t h2exp2(uint32_t a) {
    uint32_t d; asm("ex2.approx.f16x2 %0, %1;" : "=r"(d) : "r"(a)); return d;
}
// fp16: D += A(m16 x k16) * B(k16 x n8), f32 accumulate
__device__ __forceinline__ void mma16(float* d, const uint32_t* a, const uint32_t* b) {
    asm volatile(
        "mma.sync.aligned.m16n8k16.row.col.f32.f16.f16.f32 "
        "{%0,%1,%2,%3}, {%4,%5,%6,%7}, {%8,%9}, {%0,%1,%2,%3};"
        : "+f"(d[0]), "+f"(d[1]), "+f"(d[2]), "+f"(d[3])
        : "r"(a[0]), "r"(a[1]), "r"(a[2]), "r"(a[3]), "r"(b[0]), "r"(b[1]));
}
__device__ __forceinline__ void cp16(uint32_t dst, const void* src) {
    asm volatile("cp.async.ca.shared.global [%0], [%1], 16;" :: "r"(dst), "l"(src));
}
__device__ __forceinline__ void cp_commit() { asm volatile("cp.async.commit_group;"); }
template<int N> __device__ __forceinline__ void cp_wait() {
    asm volatile("cp.async.wait_group %0;" :: "n"(N));
}

// ---------------------------------------------------------------------------
// Fused prep: blocks 0-23 transpose W to fp16 g_Wt; blocks 24-31 run the
// per-batch key-compaction scan (tidx, total, nt, bias; zero K/V pad region).
// ---------------------------------------------------------------------------
__global__ void __launch_bounds__(256) prep_kernel(
    const float* __restrict__ Wq, const float* __restrict__ Wk,
    const float* __restrict__ Wv, const int* __restrict__ pm_g)
{
    int tid = threadIdx.x;
    if (blockIdx.x < 24) {
        __shared__ float tile[64][65];
        int which = blockIdx.x >> 3;
        int kb    = (blockIdx.x & 7) * 64;
        const float* W = (which == 0) ? Wq : ((which == 1) ? Wk : Wv);
        __half* Wt = g_Wt + (size_t)which * 64 * DM;

        #pragma unroll
        for (int i = 0; i < 16; i++) {
            int idx = tid + i * 256;
            int k = idx >> 6, n = idx & 63;
            tile[k][n] = W[(size_t)(kb + k) * 64 + n];
        }
        __syncthreads();
        #pragma unroll
        for (int i = 0; i < 16; i++) {
            int idx = tid + i * 256;
            int n = idx >> 6, k = idx & 63;
            Wt[(size_t)n * DM + kb + k] = __float2half_rn(tile[k][n]);
        }
    } else {
        int b = blockIdx.x - 24;
        const int* m = pm_g + (size_t)b * TT;
        int base = tid * 16;

        int v[16];
        int cnt = 0;
        #pragma unroll
        for (int i = 0; i < 16; i += 4) {
            int4 mm = *(const int4*)(m + base + i);
            v[i] = (mm.x == 0); v[i + 1] = (mm.y == 0);
            v[i + 2] = (mm.z == 0); v[i + 3] = (mm.w == 0);
            cnt += v[i] + v[i + 1] + v[i + 2] + v[i + 3];
        }

        __shared__ int ssum[256];
        ssum[tid] = cnt;
        __syncthreads();
        for (int off = 1; off < 256; off <<= 1) {
            int t = (tid >= off) ? ssum[tid - off] : 0;
            __syncthreads();
            ssum[tid] += t;
            __syncthreads();
        }
        int total = ssum[255];
        int o = ssum[tid] - cnt;   // exclusive prefix

        int* tidx = g_tidx + (size_t)b * TT;
        #pragma unroll
        for (int i = 0; i < 16; i++) {
            if (v[i]) tidx[o++] = base + i;
        }
        // tail: fill with 0 (safe gather index) up to next 128 multiple
        int tileEnd = ((total + 127) >> 7) << 7;
        for (int j = total + tid; j < tileEnd; j += 256) tidx[j] = 0;

        int nt = (total + 63) >> 6;
        if (tid == 0) { g_nt[b] = nt; g_total[b] = total; }
        int padEnd = nt * 64;

        // compacted bias pairs: 0 for valid, -64k (0xFBFF) for tail pads
        uint32_t* bc = g_biasc + (size_t)b * (TT / 2);
        for (int j2 = tid; j2 < (padEnd >> 1); j2 += 256) {
            int j0 = 2 * j2;
            uint32_t w = 0;
            if (j0 >= total)     w |= 0x0000FBFFu;
            if (j0 + 1 >= total) w |= 0xFBFF0000u;
            bc[j2] = w;
        }

        // zero K pad rows
        for (int j = total + tid; j < padEnd; j += 256) {
            uint32_t* kr = (uint32_t*)(g_Kc + ((size_t)b * TT + j) * 64);
            #pragma unroll
            for (int c = 0; c < 32; c++) kr[c] = 0;
        }
        // zero Vt pad columns
        int P = padEnd - total;
        if (P > 0) {
            for (int x = tid; x < P * 64; x += 256) {
                int d = x / P, j = total + x % P;
                g_Vtc[((size_t)b * 64 + d) * TT + j] = __ushort_as_half((unsigned short)0);
            }
        }
    }
}

// ---------------------------------------------------------------------------
// Projection, fp16 m16n8k16, 2-stage cp.async pipeline.
// which==0: full Q (blockIdx.x = global row tile).
// which==1/2: COMPACTED K/V — blockIdx.x = (b<<5)|tile over compacted rows,
// X rows gathered via g_tidx (staged in SMEM); blocks past total_b exit.
// ---------------------------------------------------------------------------
#define PX_PAD 36
#define PWT_STR 40
#define P_X0 0
#define P_X1 18432
#define P_W0 36864
#define P_W1 41984
#define P_TIDX 47104                 // 128 ints = 512 B
#define P_TOT  47616

__global__ void __launch_bounds__(256, 2) proj_kernel(
    const float* __restrict__ Xq, const float* __restrict__ Xk, const float* __restrict__ Xv)
{
    extern __shared__ char sm[];
    uint32_t smb = smem_to_u32(sm);

    const int which = blockIdx.y;
    const int tid = threadIdx.x, lane = tid & 31, warp = tid >> 5;
    const int r4 = lane >> 2, k4 = lane & 3;

    const float* X;
    int rowBase;           // row tile start (global for Q, compacted for K/V)
    int b = 0, total = 0;
    int* tidx_s = (int*)(sm + P_TIDX);

    if (which == 0) {
        X = Xq;
        rowBase = blockIdx.x * 128;
    } else {
        b = blockIdx.x >> 5;
        int tile = blockIdx.x & 31;
        total = g_total[b];
        rowBase = tile * 128;
        if (rowBase >= total) return;
        X = ((which == 1) ? Xk : Xv) + (size_t)b * TT * DM;
        // stage the 128 gather indices
        if (tid < 128) tidx_s[tid] = g_tidx[(size_t)b * TT + rowBase + tid];
        __syncthreads();
    }
    const __half* Wt = g_Wt + (size_t)which * 64 * DM;

    auto load_chunk = [&](int ch) {
        uint32_t xd = smb + ((ch & 1) ? P_X1 : P_X0);
        uint32_t wd = smb + ((ch & 1) ? P_W1 : P_W0);
        #pragma unroll
        for (int i = 0; i < 4; i++) {
            int idx = tid + i * 256;
            int row = idx >> 3, c = idx & 7;
            const float* src;
            if (which == 0)
                src = X + (size_t)(rowBase + row) * DM + ch * 32 + c * 4;
            else
                src = X + (size_t)tidx_s[row] * DM + ch * 32 + c * 4;
            cp16(xd + row * (PX_PAD * 4) + c * 16, src);
        }
        {
            int n = tid >> 2, seg = tid & 3;
            cp16(wd + n * (PWT_STR * 2) + seg * 16, Wt + (size_t)n * DM + ch * 32 + seg * 8);
        }
        cp_commit();
    };

    float acc[8][4];
    #pragma unroll
    for (int nb = 0; nb < 8; nb++)
        #pragma unroll
        for (int i = 0; i < 4; i++) acc[nb][i] = 0.0f;

    load_chunk(0);
    for (int ch = 0; ch < 16; ch++) {
        if (ch > 0) __syncthreads();
        if (ch < 15) load_chunk(ch + 1);
        if (ch < 15) cp_wait<1>(); else cp_wait<0>();
        __syncthreads();

        const float*  Xs = (const float*)(sm + ((ch & 1) ? P_X1 : P_X0));
        const __half* Ws = (const __half*)(sm + ((ch & 1) ? P_W1 : P_W0));

        #pragma unroll
        for (int ks = 0; ks < 2; ks++) {
            int c0 = ks * 16 + 2 * k4;
            const float* xp  = Xs + (warp * 16 + r4) * PX_PAD + c0;
            const float* xp8 = xp + 8 * PX_PAD;
            uint32_t a[4] = {
                pack_h2(xp[0],  xp[1]),
                pack_h2(xp8[0], xp8[1]),
                pack_h2(xp[8],  xp[9]),
                pack_h2(xp8[8], xp8[9])
            };
            #pragma unroll
            for (int nb = 0; nb < 8; nb++) {
                const __half* wn = Ws + (nb * 8 + r4) * PWT_STR + c0;
                uint32_t bb[2] = { *(const uint32_t*)(wn), *(const uint32_t*)(wn + 8) };
                mma16(acc[nb], a, bb);
            }
        }
    }

    // epilogue
    if (which == 0) {
        int m0 = rowBase + warp * 16 + r4;
        const float sc = 0.044194173824159216f * 1.4426950408889634f;
        __half* yp = g_Qh + (size_t)m0 * 64;
        #pragma unroll
        for (int nb = 0; nb < 8; nb++) {
            int c = nb * 8 + 2 * k4;
            *(uint32_t*)(yp + c)          = pack_h2(acc[nb][0] * sc, acc[nb][1] * sc);
            *(uint32_t*)(yp + 8 * 64 + c) = pack_h2(acc[nb][2] * sc, acc[nb][3] * sc);
        }
    } else {
        int j0 = rowBase + warp * 16 + r4;    // compacted row; second is j0+8
        int j1 = j0 + 8;
        bool w0 = j0 < total, w1 = j1 < total;
        if (which == 1) {
            __half* y0 = g_Kc + ((size_t)b * TT + j0) * 64;
            __half* y1 = g_Kc + ((size_t)b * TT + j1) * 64;
            #pragma unroll
            for (int nb = 0; nb < 8; nb++) {
                int c = nb * 8 + 2 * k4;
                if (w0) *(uint32_t*)(y0 + c) = pack_h2(acc[nb][0], acc[nb][1]);
                if (w1) *(uint32_t*)(y1 + c) = pack_h2(acc[nb][2], acc[nb][3]);
            }
        } else {
            __half* vb = g_Vtc + (size_t)b * 64 * TT;
            #pragma unroll
            for (int nb = 0; nb < 8; nb++) {
                int d = nb * 8 + 2 * k4;
                if (w0) {
                    vb[(size_t)d * TT + j0]       = __float2half_rn(acc[nb][0]);
                    vb[(size_t)(d + 1) * TT + j0] = __float2half_rn(acc[nb][1]);
                }
                if (w1) {
                    vb[(size_t)d * TT + j1]       = __float2half_rn(acc[nb][2]);
                    vb[(size_t)(d + 1) * TT + j1] = __float2half_rn(acc[nb][3]);
                }
            }
        }
    }
}

// ---------------------------------------------------------------------------
// Flash attention over COMPACTED keys, fp16 m16n8k16. CTA = (128 q-rows,
// batch); 4 warps x m32 x n64; dynamic tile count g_nt[b] (~32); 2 CTAs/SM.
// Softmax f16x2 with compacted bias (valid=0, pads=-64k); l via tensor core.
// ---------------------------------------------------------------------------
#define AQ_STR 72
#define AK_STR 72
#define AV_STR 72
#define A_BIAS 0                       // 2048 u32 = 8192 B
#define A_Q    8192
#define A_K0   26624
#define A_K1   35840
#define A_V0   45056
#define A_V1   54272
#define A_TOT  63488

__global__ void __launch_bounds__(128, 2) attn_kernel(float* __restrict__ out)
{
    extern __shared__ char sm[];
    uint32_t smb = smem_to_u32(sm);

    const int tid = threadIdx.x, lane = tid & 31, warp = tid >> 5;
    const int b = blockIdx.y, qBase = blockIdx.x * 128;
    const int r4 = lane >> 2, k4 = lane & 3;

    const __half* gK  = g_Kc  + (size_t)b * TT * 64;
    const __half* gVt = g_Vtc + (size_t)b * 64 * TT;
    const int nt = g_nt[b];

    // stage Q tile (fp16, pre-scaled) — its own commit group
    {
        const __half* src = g_Qh + ((size_t)b * TT + qBase) * 64;
        #pragma unroll
        for (int i = 0; i < 8; i++) {
            int idx = tid + i * 128;
            int row = idx >> 3, c = idx & 7;
            cp16(smb + A_Q + row * (AQ_STR * 2) + c * 16, src + row * 64 + c * 8);
        }
        cp_commit();
    }

    auto load_tile = [&](int t) {
        int base = t * 64;
        uint32_t kd = smb + ((t & 1) ? A_K1 : A_K0);
        uint32_t vd = smb + ((t & 1) ? A_V1 : A_V0);
        #pragma unroll
        for (int i = 0; i < 4; i++) {
            int idx = tid + i * 128;
            int row = idx >> 3, c = idx & 7;
            cp16(kd + row * (AK_STR * 2) + c * 16, gK + (size_t)(base + row) * 64 + c * 8);
        }
        #pragma unroll
        for (int i = 0; i < 4; i++) {
            int idx = tid + i * 128;
            int d = idx >> 3, c = idx & 7;
            cp16(vd + d * (AV_STR * 2) + c * 16, gVt + (size_t)d * TT + base + c * 8);
        }
        cp_commit();
    };

    load_tile(0);

    // stage compacted bias (nt*32 u32)
    {
        uint32_t* b16 = (uint32_t*)(sm + A_BIAS);
        const uint32_t* src = g_biasc + (size_t)b * (TT / 2);
        for (int i = tid; i < nt * 32; i += 128) b16[i] = src[i];
    }

    cp_wait<1>();
    __syncthreads();

    // persistent Q fragments: 2 m16-blocks (rows warp*32 .. +31)
    uint32_t Qr[2][4][4];
    {
        const __half* Qs = (const __half*)(sm + A_Q);
        #pragma unroll
        for (int m2 = 0; m2 < 2; m2++) {
            int r0 = warp * 32 + m2 * 16 + r4;
            #pragma unroll
            for (int ks = 0; ks < 4; ks++) {
                int c0 = ks * 16 + 2 * k4;
                Qr[m2][ks][0] = *(const uint32_t*)(Qs + r0 * AQ_STR + c0);
                Qr[m2][ks][1] = *(const uint32_t*)(Qs + (r0 + 8) * AQ_STR + c0);
                Qr[m2][ks][2] = *(const uint32_t*)(Qs + r0 * AQ_STR + c0 + 8);
                Qr[m2][ks][3] = *(const uint32_t*)(Qs + (r0 + 8) * AQ_STR + c0 + 8);
            }
        }
    }

    float o[2][8][4];
    float la[4] = {0.f, 0.f, 0.f, 0.f};
    float lb[4] = {0.f, 0.f, 0.f, 0.f};
    #pragma unroll
    for (int m2 = 0; m2 < 2; m2++)
        #pragma unroll
        for (int nb = 0; nb < 8; nb++)
            #pragma unroll
            for (int i = 0; i < 4; i++) o[m2][nb][i] = 0.0f;

    const uint32_t ONES = 0x3C003C00u;
    const uint32_t onesb[2] = { ONES, ONES };

    for (int t = 0; t < nt; t++) {
        if (t > 0) __syncthreads();
        if (t < nt - 1) load_tile(t + 1);
        if (t < nt - 1) cp_wait<1>(); else cp_wait<0>();
        __syncthreads();

        const __half* Ks = (const __half*)(sm + ((t & 1) ? A_K1 : A_K0));
        const __half* Vs = (const __half*)(sm + ((t & 1) ? A_V1 : A_V0));
        const uint32_t* bias16 = (const uint32_t*)(sm + A_BIAS) + t * 32;

        // ---- S = Q @ K^T: each K B-frag feeds BOTH m16 halves ----
        float s[2][8][4];
        #pragma unroll
        for (int m2 = 0; m2 < 2; m2++)
            #pragma unroll
            for (int nb = 0; nb < 8; nb++) {
                s[m2][nb][0] = 0.0f; s[m2][nb][1] = 0.0f;
                s[m2][nb][2] = 0.0f; s[m2][nb][3] = 0.0f;
            }
        #pragma unroll
        for (int ks = 0; ks < 4; ks++) {
            int c0 = ks * 16 + 2 * k4;
            #pragma unroll
            for (int nb = 0; nb < 8; nb++) {
                const __half* kk = Ks + (nb * 8 + r4) * AK_STR + c0;
                uint32_t bb[2] = { *(const uint32_t*)(kk), *(const uint32_t*)(kk + 8) };
                mma16(s[0][nb], Qr[0][ks], bb);
                mma16(s[1][nb], Qr[1][ks], bb);
            }
        }

        // ---- softmax in f16x2 ----
        uint32_t plo[2][8], phi[2][8];
        #pragma unroll
        for (int nb = 0; nb < 8; nb++) {
            uint32_t bv = bias16[nb * 4 + k4];
            #pragma unroll
            for (int m2 = 0; m2 < 2; m2++) {
                plo[m2][nb] = h2exp2(hadd2(pack_h2(s[m2][nb][0], s[m2][nb][1]), bv));
                phi[m2][nb] = h2exp2(hadd2(pack_h2(s[m2][nb][2], s[m2][nb][3]), bv));
            }
        }

        // ---- O += P @ V; l += P @ 1 ----
        #pragma unroll
        for (int nbS = 0; nbS < 4; nbS++) {
            uint32_t a0[4] = { plo[0][2 * nbS], phi[0][2 * nbS],
                               plo[0][2 * nbS + 1], phi[0][2 * nbS + 1] };
            uint32_t a1[4] = { plo[1][2 * nbS], phi[1][2 * nbS],
                               plo[1][2 * nbS + 1], phi[1][2 * nbS + 1] };
            int sc = nbS * 16 + 2 * k4;
            #pragma unroll
            for (int nb = 0; nb < 8; nb++) {
                const __half* vp = Vs + (nb * 8 + r4) * AV_STR + sc;
                uint32_t bb[2] = { *(const uint32_t*)(vp), *(const uint32_t*)(vp + 8) };
                mma16(o[0][nb], a0, bb);
                mma16(o[1][nb], a1, bb);
            }
            mma16(la, a0, onesb);
            mma16(lb, a1, onesb);
        }
    }

    float inv[2][2];
    inv[0][0] = 1.0f / la[0]; inv[0][1] = 1.0f / la[2];
    inv[1][0] = 1.0f / lb[0]; inv[1][1] = 1.0f / lb[2];

    #pragma unroll
    for (int m2 = 0; m2 < 2; m2++) {
        float* op = out + ((size_t)b * TT + qBase + warp * 32 + m2 * 16) * 64;
        #pragma unroll
        for (int nb = 0; nb < 8; nb++) {
            int c = nb * 8 + 2 * k4;
            *(float2*)(op + r4 * 64 + c) =
                make_float2(o[m2][nb][0] * inv[m2][0], o[m2][nb][1] * inv[m2][0]);
            *(float2*)(op + (r4 + 8) * 64 + c) =
                make_float2(o[m2][nb][2] * inv[m2][1], o[m2][nb][3] * inv[m2][1]);
        }
    }
}

// ---------------------------------------------------------------------------
// kernel_launch: inputs (metadata order): k, v, q, pad_mask, Wk, Wq, Wv
// ---------------------------------------------------------------------------
extern "C" void kernel_launch(void* const* d_in, const int* in_sizes, int n_in,
                              void* d_out, int out_size)
{
    const float* k        = (const float*)d_in[0];
    const float* v        = (const float*)d_in[1];
    const float* q        = (const float*)d_in[2];
    const int*   pad_mask = (const int*)d_in[3];
    const float* Wk       = (const float*)d_in[4];
    const float* Wq       = (const float*)d_in[5];
    const float* Wv       = (const float*)d_in[6];
    float* out = (float*)d_out;

    prep_kernel<<<32, 256>>>(Wq, Wk, Wv, pad_mask);

    cudaFuncSetAttribute(proj_kernel, cudaFuncAttributeMaxDynamicSharedMemorySize, P_TOT);
    dim3 pg(BB * TT / 128, 3);   // which=0 uses all 256; which=1/2 exit past total
    proj_kernel<<<pg, 256, P_TOT>>>(q, k, v);

    cudaFuncSetAttribute(attn_kernel, cudaFuncAttributeMaxDynamicSharedMemorySize, A_TOT);
    dim3 ag(TT / 128, BB);
    attn_kernel<<<ag, 128, A_TOT>>>(out);
}